// round 8
// baseline (speedup 1.0000x reference)
#include <cuda_runtime.h>
#include <cuda_bf16.h>

// CapsuleModel2: sigmoid(segment_mean(feats[point_idx]) @ W + b)
// R8: project-then-pool. mean(X) @ W == mean(X @ W), so project each of the
// 65536 grid cells ONCE (K1: Y = feats @ W, 71 MB read + 0.7 GFLOP), then
// gather/segment-mean the 19-dim projections (K2: 40 MB instead of 570 MB).

#define NCP        20                     // padded Y row stride (floats)
#define GCELLS_MAX 65536
__device__ float g_Y[GCELLS_MAX * NCP];   // 5.24 MB scratch (allocation-free)

typedef unsigned long long ull;
__device__ __forceinline__ ull f2fma(ull a, ull b, ull c) {
    ull r; asm("fma.rn.f32x2 %0, %1, %2, %3;" : "=l"(r) : "l"(a), "l"(b), "l"(c));
    return r;
}
__device__ __forceinline__ ull f2add(ull a, ull b) {
    ull r; asm("add.rn.f32x2 %0, %1, %2;" : "=l"(r) : "l"(a), "l"(b));
    return r;
}
__device__ __forceinline__ ull f2pack(float lo, float hi) {
    ull r; asm("mov.b64 %0, {%1, %2};" : "=l"(r) : "f"(lo), "f"(hi));
    return r;
}
__device__ __forceinline__ float2 f2unpack(ull v) {
    float2 p; asm("mov.b64 {%0, %1}, %2;" : "=f"(p.x), "=f"(p.y) : "l"(v));
    return p;
}

// ===================== K1: Y[g, c] = feats[g, :] @ W[:, c] =====================
#define K1_BLOCK 160                      // 5 warps; warp w -> cols 4w..4w+3
#define K1_ROWS  32                       // lane = row within tile
#define K1_FPAD  274                      // even pad: conflict-free LDS.64 on f

__global__ void __launch_bounds__(K1_BLOCK)
project_kernel(const float* __restrict__ feats, const float* __restrict__ Wm,
               int D, int NC, int Gcells)
{
    extern __shared__ float sm[];
    float* s_f = sm;                      // [K1_ROWS][K1_FPAD]
    float* s_w = sm + K1_ROWS * K1_FPAD;  // [D][NCP], cols >= NC zero-padded

    const int tid  = threadIdx.x, lane = tid & 31, w = tid >> 5;
    const int row0 = blockIdx.x * K1_ROWS;
    const int rows = min(K1_ROWS, Gcells - row0);

    for (int i = tid; i < D * NCP; i += K1_BLOCK) {
        const int d = i / NCP, c = i - d * NCP;
        s_w[i] = (c < NC) ? __ldg(&Wm[d * NC + c]) : 0.f;
    }
    {   // stage feats tile (rows contiguous in global -> linear float4 copy)
        const float4* src = (const float4*)(feats + (size_t)row0 * D);
        const int nf4 = rows * D / 4;
        for (int i = tid; i < nf4; i += K1_BLOCK) {
            const float4 v = __ldg(src + i);
            const int e = i * 4;
            const int r = e / D, c = e - r * D;
            float* dst = s_f + r * K1_FPAD + c;
            *(float2*)(dst)     = make_float2(v.x, v.y);
            *(float2*)(dst + 2) = make_float2(v.z, v.w);
        }
    }
    __syncthreads();

    const int c0 = 4 * w;
    const float* frow = s_f + lane * K1_FPAD;
    ull aA0 = 0, aA1 = 0, aB0 = 0, aB1 = 0;   // (colpair A/B) x (even/odd d chains)
    #pragma unroll 4
    for (int d = 0; d < D; d += 2) {
        const ull fp = *(const ull*)&frow[d];     // {f[d], f[d+1]}
        const float2 f = f2unpack(fp);
        const ull v0 = f2pack(f.x, f.x);
        const ull v1 = f2pack(f.y, f.y);
        const float* wr0 = s_w + d * NCP + c0;
        const ull wA0 = *(const ull*)(wr0);
        const ull wB0 = *(const ull*)(wr0 + 2);
        const ull wA1 = *(const ull*)(wr0 + NCP);
        const ull wB1 = *(const ull*)(wr0 + NCP + 2);
        aA0 = f2fma(v0, wA0, aA0);
        aB0 = f2fma(v0, wB0, aB0);
        aA1 = f2fma(v1, wA1, aA1);
        aB1 = f2fma(v1, wB1, aB1);
    }
    const float2 A  = f2unpack(f2add(aA0, aA1));
    const float2 Bv = f2unpack(f2add(aB0, aB1));
    if (lane < rows) {
        float* yr = g_Y + (size_t)(row0 + lane) * NCP + c0;
        if (c0 + 0 < NC) yr[0] = A.x;
        if (c0 + 1 < NC) yr[1] = A.y;
        if (c0 + 2 < NC) yr[2] = Bv.x;
        if (c0 + 3 < NC) yr[3] = Bv.y;
    }
}

// ============ K2: out[s] = sigmoid(mean_{p in seg s} Y[idx_p] + b) ============
#define K2_BLOCK 256                      // 8 warps; lane = class col

__global__ void __launch_bounds__(K2_BLOCK)
pool_kernel(const float* __restrict__ bias, const int* __restrict__ point_idx,
            const int* __restrict__ segment_ids, float* __restrict__ out,
            int P, int NC, int NI)
{
    __shared__ int   s_b[2];
    __shared__ int   s_i[K2_BLOCK];
    __shared__ float s_part[8][NCP];

    const int tid = threadIdx.x, lane = tid & 31, w = tid >> 5;
    const int seg = blockIdx.x;

    // warps 0,1: 32-ary lower_bound(seg + w) over sorted segment_ids
    if (w < 2) {
        const int target = seg + w;
        int lo = 0, hi = P;
        while (hi - lo > 32) {
            const int step = ((hi - lo) + 31) >> 5;
            int m = lo + lane * step;
            m = min(m, hi - 1);
            const bool lt = (__ldg(&segment_ids[m]) < target);
            const int k = __popc(__ballot_sync(0xffffffffu, lt));
            const int nlo = (k == 0)  ? lo : min(lo + (k - 1) * step + 1, hi);
            const int nhi = (k == 32) ? hi : min(lo + k * step, hi);
            lo = nlo; hi = nhi;
        }
        {
            const int m = lo + lane;
            const bool lt = (m < hi) ? (__ldg(&segment_ids[m]) < target) : false;
            lo += __popc(__ballot_sync(0xffffffffu, lt));
        }
        if (lane == 0) s_b[w] = lo;
    }
    __syncthreads();

    const int start = s_b[0], end = s_b[1], cnt = end - start;
    const bool cact = (lane < NC);
    float acc = 0.f;

    for (int base = start; base < end; base += K2_BLOCK) {
        const int n = min(K2_BLOCK, end - base);
        if (tid < n) s_i[tid] = __ldg(&point_idx[base + tid]);
        __syncthreads();
        if (cact) {
            int i = w;
            for (; i + 24 < n; i += 32) {        // 4 independent gathers in flight
                const int i0 = s_i[i], i1 = s_i[i + 8];
                const int i2 = s_i[i + 16], i3 = s_i[i + 24];
                const float y0 = __ldg(&g_Y[(size_t)i0 * NCP + lane]);
                const float y1 = __ldg(&g_Y[(size_t)i1 * NCP + lane]);
                const float y2 = __ldg(&g_Y[(size_t)i2 * NCP + lane]);
                const float y3 = __ldg(&g_Y[(size_t)i3 * NCP + lane]);
                acc += (y0 + y1) + (y2 + y3);
            }
            for (; i < n; i += 8)
                acc += __ldg(&g_Y[(size_t)s_i[i] * NCP + lane]);
        }
        __syncthreads();
    }

    if (cact) s_part[w][lane] = acc;
    __syncthreads();
    if (w == 0 && cact) {
        float s = 0.f;
        #pragma unroll
        for (int j = 0; j < 8; ++j) s += s_part[j][lane];
        const float x = s / (float)max(cnt, 1) + __ldg(&bias[lane]);
        out[(size_t)seg * NC + lane] = 1.0f / (1.0f + __expf(-x));
    }
}

extern "C" void kernel_launch(void* const* d_in, const int* in_sizes, int n_in,
                              void* d_out, int out_size)
{
    const float* feats       = (const float*)d_in[0];
    const float* Wm          = (const float*)d_in[1];
    const float* bias        = (const float*)d_in[2];
    const int*   point_idx   = (const int*)  d_in[3];
    const int*   segment_ids = (const int*)  d_in[4];
    float*       out         = (float*)      d_out;

    const int NC     = in_sizes[2];              // 19
    const int D      = in_sizes[1] / NC;         // 272
    const int P      = in_sizes[3];              // 524288
    const int NI     = out_size / NC;            // 4096
    const int Gcells = in_sizes[0] / D;          // 65536

    const int k1_smem = (K1_ROWS * K1_FPAD + D * NCP) * (int)sizeof(float);
    cudaFuncSetAttribute(project_kernel,
                         cudaFuncAttributeMaxDynamicSharedMemorySize, k1_smem);

    project_kernel<<<(Gcells + K1_ROWS - 1) / K1_ROWS, K1_BLOCK, k1_smem>>>(
        feats, Wm, D, NC, Gcells);
    pool_kernel<<<NI, K2_BLOCK>>>(bias, point_idx, segment_ids, out, P, NC, NI);
}

// round 9
// speedup vs baseline: 1.1727x; 1.1727x over previous
#include <cuda_runtime.h>
#include <cuda_bf16.h>

// CapsuleModel2: sigmoid(segment_mean(feats[point_idx]) @ W + b)
// R9: project-then-pool, both kernels rebuilt.
//  K1: thread-per-2-rows register GEMM, W broadcast from smem, k-chunked f tile.
//  K2: persistent CTAs (~7 segs each), warp-parallel boundary search, 8-deep gather.

#define NCP        20                     // padded Y row stride (floats)
#define GCELLS_MAX 65536
__device__ float g_Y[GCELLS_MAX * NCP];   // 5.24 MB scratch (allocation-free)

typedef unsigned long long ull;
__device__ __forceinline__ ull f2fma(ull a, ull b, ull c) {
    ull r; asm("fma.rn.f32x2 %0, %1, %2, %3;" : "=l"(r) : "l"(a), "l"(b), "l"(c));
    return r;
}
__device__ __forceinline__ ull f2pack(float lo, float hi) {
    ull r; asm("mov.b64 %0, {%1, %2};" : "=l"(r) : "f"(lo), "f"(hi));
    return r;
}
__device__ __forceinline__ float2 f2unpack(ull v) {
    float2 p; asm("mov.b64 {%0, %1}, %2;" : "=f"(p.x), "=f"(p.y) : "l"(v));
    return p;
}

// ===================== K1: Y[g, :] = feats[g, :] @ W  =====================
#define K1_BLOCK 128
#define K1_ROWS  256                      // rows/CTA; thread t -> rows t, t+128
#define K1_KC    68                       // k-chunk width
#define K1_FPAD  70                       // f tile stride: even (LDS.64 align), 2-way max

__global__ void __launch_bounds__(K1_BLOCK)
project_kernel(const float* __restrict__ feats, const float* __restrict__ Wm,
               int D, int NC, int Gcells)
{
    extern __shared__ float sm[];
    float* s_f = sm;                       // [K1_ROWS][K1_FPAD]
    float* s_w = sm + K1_ROWS * K1_FPAD;   // [D][NCP], cols >= NC zeroed

    const int tid  = threadIdx.x;
    const int row0 = blockIdx.x * K1_ROWS;

    // stage W once (broadcast source)
    for (int i = tid; i < D * NCP; i += K1_BLOCK) {
        const int d = i / NCP, c = i - d * NCP;
        s_w[i] = (c < NC) ? __ldg(&Wm[d * NC + c]) : 0.f;
    }

    ull accA[NCP / 2], accB[NCP / 2];
    #pragma unroll
    for (int j = 0; j < NCP / 2; ++j) { accA[j] = 0ull; accB[j] = 0ull; }

    const int rA = tid, rB = tid + K1_BLOCK;           // local rows
    const int rows = min(K1_ROWS, Gcells - row0);

    for (int c0 = 0; c0 < D; c0 += K1_KC) {
        const int kc = min(K1_KC, D - c0);
        __syncthreads();
        {   // stage f chunk: rows x kc floats (16B loads, 2x8B stores)
            const int nf4 = rows * (kc >> 2);
            const int q4  = kc >> 2;
            for (int i = tid; i < nf4; i += K1_BLOCK) {
                const int r = i / q4, k = (i - r * q4) << 2;
                const float4 v = __ldg((const float4*)
                    (feats + (size_t)(row0 + r) * D + c0 + k));
                float* dst = s_f + r * K1_FPAD + k;
                *(float2*)(dst)     = make_float2(v.x, v.y);
                *(float2*)(dst + 2) = make_float2(v.z, v.w);
            }
        }
        __syncthreads();

        const float* fa = s_f + rA * K1_FPAD;
        const float* fb = s_f + rB * K1_FPAD;
        #pragma unroll 2
        for (int kk = 0; kk < kc; kk += 2) {
            const float2 pA = *(const float2*)&fa[kk];
            const float2 pB = *(const float2*)&fb[kk];
            const ull a0 = f2pack(pA.x, pA.x), a1 = f2pack(pA.y, pA.y);
            const ull b0 = f2pack(pB.x, pB.x), b1 = f2pack(pB.y, pB.y);
            const float* w0 = s_w + (c0 + kk) * NCP;
            #pragma unroll
            for (int j = 0; j < NCP / 2; ++j) {
                const ull wlo = *(const ull*)(w0 + 2 * j);          // broadcast
                const ull whi = *(const ull*)(w0 + NCP + 2 * j);    // broadcast
                accA[j] = f2fma(a0, wlo, accA[j]);
                accA[j] = f2fma(a1, whi, accA[j]);
                accB[j] = f2fma(b0, wlo, accB[j]);
                accB[j] = f2fma(b1, whi, accB[j]);
            }
        }
    }

    // epilogue: 5 STG.128 per row
    #pragma unroll 2
    for (int h = 0; h < 2; ++h) {
        const int r = row0 + (h ? rB : rA);
        if (r < Gcells) {
            const ull* acc = h ? accB : accA;
            float4* yr = (float4*)(g_Y + (size_t)r * NCP);
            #pragma unroll
            for (int j = 0; j < NCP / 4; ++j) {
                const float2 e = f2unpack(acc[2 * j]);
                const float2 o = f2unpack(acc[2 * j + 1]);
                yr[j] = make_float4(e.x, e.y, o.x, o.y);
            }
        }
    }
}

// ============ K2: out[s] = sigmoid(mean_{p in seg s} Y[idx_p] + b) ============
#define K2_BLOCK 256                      // 8 warps; lane = class col
#define K2_MAXSEG 12

__global__ void __launch_bounds__(K2_BLOCK)
pool_kernel(const float* __restrict__ bias, const int* __restrict__ point_idx,
            const int* __restrict__ segment_ids, float* __restrict__ out,
            int P, int NC, int NI, int G2)
{
    __shared__ int   s_b[K2_MAXSEG + 1];
    __shared__ int   s_i[K2_BLOCK];
    __shared__ float s_part[8][NCP];

    const int tid = threadIdx.x, lane = tid & 31, w = tid >> 5;

    const int lo_seg = (int)(((long long)blockIdx.x)     * NI / G2);
    const int hi_seg = (int)(((long long)blockIdx.x + 1) * NI / G2);
    const int nseg   = hi_seg - lo_seg;
    if (nseg <= 0) return;

    // all nseg+1 boundaries in parallel: warp w -> 32-ary lower_bound(lo_seg+w)
    for (int t = w; t <= nseg; t += 8) {
        const int target = lo_seg + t;
        int lo = 0, hi = P;
        while (hi - lo > 32) {
            const int step = ((hi - lo) + 31) >> 5;
            int m = lo + lane * step;
            m = min(m, hi - 1);
            const bool lt = (__ldg(&segment_ids[m]) < target);
            const int k = __popc(__ballot_sync(0xffffffffu, lt));
            const int nlo = (k == 0)  ? lo : min(lo + (k - 1) * step + 1, hi);
            const int nhi = (k == 32) ? hi : min(lo + k * step, hi);
            lo = nlo; hi = nhi;
        }
        {
            const int m = lo + lane;
            const bool lt = (m < hi) ? (__ldg(&segment_ids[m]) < target) : false;
            lo += __popc(__ballot_sync(0xffffffffu, lt));
        }
        if (lane == 0) s_b[t] = lo;
    }
    __syncthreads();

    const bool cact = (lane < NC);

    for (int s = 0; s < nseg; ++s) {
        const int seg = lo_seg + s;
        const int start = s_b[s], end = s_b[s + 1], cnt = end - start;
        float acc = 0.f;

        for (int base = start; base < end; base += K2_BLOCK) {
            const int n = min(K2_BLOCK, end - base);
            if (tid < n) s_i[tid] = __ldg(&point_idx[base + tid]);
            __syncthreads();
            if (cact) {
                int i = w;
                for (; i + 56 < n; i += 64) {      // 8 independent gathers in flight
                    const int i0 = s_i[i],      i1 = s_i[i + 8];
                    const int i2 = s_i[i + 16], i3 = s_i[i + 24];
                    const int i4 = s_i[i + 32], i5 = s_i[i + 40];
                    const int i6 = s_i[i + 48], i7 = s_i[i + 56];
                    const float y0 = __ldg(&g_Y[(size_t)i0 * NCP + lane]);
                    const float y1 = __ldg(&g_Y[(size_t)i1 * NCP + lane]);
                    const float y2 = __ldg(&g_Y[(size_t)i2 * NCP + lane]);
                    const float y3 = __ldg(&g_Y[(size_t)i3 * NCP + lane]);
                    const float y4 = __ldg(&g_Y[(size_t)i4 * NCP + lane]);
                    const float y5 = __ldg(&g_Y[(size_t)i5 * NCP + lane]);
                    const float y6 = __ldg(&g_Y[(size_t)i6 * NCP + lane]);
                    const float y7 = __ldg(&g_Y[(size_t)i7 * NCP + lane]);
                    acc += ((y0 + y1) + (y2 + y3)) + ((y4 + y5) + (y6 + y7));
                }
                for (; i < n; i += 8)
                    acc += __ldg(&g_Y[(size_t)s_i[i] * NCP + lane]);
            }
            __syncthreads();
        }

        if (cact) s_part[w][lane] = acc;
        __syncthreads();
        if (w == 0 && cact) {
            float t = 0.f;
            #pragma unroll
            for (int j = 0; j < 8; ++j) t += s_part[j][lane];
            const float x = t / (float)max(cnt, 1) + __ldg(&bias[lane]);
            out[(size_t)seg * NC + lane] = 1.0f / (1.0f + __expf(-x));
        }
        __syncthreads();
    }
}

extern "C" void kernel_launch(void* const* d_in, const int* in_sizes, int n_in,
                              void* d_out, int out_size)
{
    const float* feats       = (const float*)d_in[0];
    const float* Wm          = (const float*)d_in[1];
    const float* bias        = (const float*)d_in[2];
    const int*   point_idx   = (const int*)  d_in[3];
    const int*   segment_ids = (const int*)  d_in[4];
    float*       out         = (float*)      d_out;

    const int NC     = in_sizes[2];              // 19
    const int D      = in_sizes[1] / NC;         // 272
    const int P      = in_sizes[3];              // 524288
    const int NI     = out_size / NC;            // 4096
    const int Gcells = in_sizes[0] / D;          // 65536

    const int k1_smem = (K1_ROWS * K1_FPAD + D * NCP) * (int)sizeof(float);
    static int attr_done = 0;
    if (!attr_done) {
        cudaFuncSetAttribute(project_kernel,
                             cudaFuncAttributeMaxDynamicSharedMemorySize, k1_smem);
        attr_done = 1;
    }

    int G2 = 152 * 4;                            // persistent pool grid
    if (G2 > NI) G2 = NI;
    while ((NI + G2 - 1) / G2 > K2_MAXSEG - 1) G2 *= 2;

    project_kernel<<<(Gcells + K1_ROWS - 1) / K1_ROWS, K1_BLOCK, k1_smem>>>(
        feats, Wm, D, NC, Gcells);
    pool_kernel<<<G2, K2_BLOCK>>>(bias, point_idx, segment_ids, out, P, NC, NI, G2);
}

// round 13
// speedup vs baseline: 1.4572x; 1.2426x over previous
#include <cuda_runtime.h>
#include <cuda_bf16.h>

// CapsuleModel2: sigmoid(segment_mean(feats[point_idx]) @ W + b)
// R10: project-then-pool.
//  K1: 2 rows/thread register GEMM; W rows read as 5x LDS.128; 56.6KB smem.
//  K2: one CTA/segment; lane->(point,piece) mapping: one LDG.128 = 6 points.

#define NCP        20                     // padded Y row stride (floats)
#define GCELLS_MAX 65536
__device__ float g_Y[GCELLS_MAX * NCP];   // 5.24 MB scratch (allocation-free)

typedef unsigned long long ull;
__device__ __forceinline__ ull f2fma(ull a, ull b, ull c) {
    ull r; asm("fma.rn.f32x2 %0, %1, %2, %3;" : "=l"(r) : "l"(a), "l"(b), "l"(c));
    return r;
}
__device__ __forceinline__ ull f2pack1(float v) {
    ull r; asm("mov.b64 %0, {%1, %1};" : "=l"(r) : "f"(v));
    return r;
}
__device__ __forceinline__ float2 f2unpack(ull v) {
    float2 p; asm("mov.b64 {%0, %1}, %2;" : "=f"(p.x), "=f"(p.y) : "l"(v));
    return p;
}

// ===================== K1: Y[g, :] = feats[g, :] @ W  =====================
#define K1_BLOCK 128
#define K1_ROWS  256                      // thread t -> rows t, t+128
#define K1_KC    32                       // k-chunk (16B-aligned chunk starts)
#define K1_FPAD  34                       // f tile stride (even -> LDS.64 ok)

__global__ void __launch_bounds__(K1_BLOCK, 2)
project_kernel(const float* __restrict__ feats, const float* __restrict__ Wm,
               int D, int NC, int Gcells)
{
    extern __shared__ float sm[];
    float* s_f = sm;                        // [K1_ROWS][K1_FPAD]
    float* s_w = sm + K1_ROWS * K1_FPAD;    // [D][NCP], 16B-aligned rows

    const int tid  = threadIdx.x;
    const int row0 = blockIdx.x * K1_ROWS;
    const int rows = min(K1_ROWS, Gcells - row0);

    // stage W once: rows of 20 floats (80B, 16B-aligned)
    for (int i = tid; i < D * NCP; i += K1_BLOCK) {
        const int d = i / NCP, c = i - d * NCP;
        s_w[i] = (c < NC) ? __ldg(&Wm[d * NC + c]) : 0.f;
    }

    ull accA[NCP / 2], accB[NCP / 2];
    #pragma unroll
    for (int j = 0; j < NCP / 2; ++j) { accA[j] = 0ull; accB[j] = 0ull; }

    const int rA = tid, rB = tid + K1_BLOCK;

    for (int c0 = 0; c0 < D; c0 += K1_KC) {
        const int kc  = min(K1_KC, D - c0);            // 32 or 16
        const int q4s = (kc == 32) ? 3 : 2;            // log2(kc/4)
        __syncthreads();
        {   // stage f chunk: coalesced float4 loads, 2x float2 smem stores
            const int nf4 = rows << q4s >> 0;          // rows * kc/4
            for (int j = tid; j < (rows << q4s); j += K1_BLOCK) {
                const int r = j >> q4s;
                const int k = (j & ((1 << q4s) - 1)) << 2;
                const float4 v = __ldg((const float4*)
                    (feats + (size_t)(row0 + r) * D + c0 + k));
                float* dst = s_f + r * K1_FPAD + k;
                *(float2*)(dst)     = make_float2(v.x, v.y);
                *(float2*)(dst + 2) = make_float2(v.z, v.w);
            }
            (void)nf4;
        }
        __syncthreads();

        const float* fa = s_f + rA * K1_FPAD;
        const float* fb = s_f + rB * K1_FPAD;
        #pragma unroll 4
        for (int kk = 0; kk < kc; kk += 2) {
            const float2 pA = *(const float2*)&fa[kk];
            const float2 pB = *(const float2*)&fb[kk];
            #pragma unroll
            for (int h = 0; h < 2; ++h) {
                const ull a = f2pack1(h ? pA.y : pA.x);
                const ull b = f2pack1(h ? pB.y : pB.x);
                const float4* wr = (const float4*)(s_w + (c0 + kk + h) * NCP);
                #pragma unroll
                for (int q = 0; q < 5; ++q) {          // 5 LDS.128 per k
                    const float4 wv = wr[q];
                    ull wp0, wp1;
                    asm("mov.b64 %0, {%1, %2};" : "=l"(wp0) : "f"(wv.x), "f"(wv.y));
                    asm("mov.b64 %0, {%1, %2};" : "=l"(wp1) : "f"(wv.z), "f"(wv.w));
                    accA[2 * q]     = f2fma(a, wp0, accA[2 * q]);
                    accA[2 * q + 1] = f2fma(a, wp1, accA[2 * q + 1]);
                    accB[2 * q]     = f2fma(b, wp0, accB[2 * q]);
                    accB[2 * q + 1] = f2fma(b, wp1, accB[2 * q + 1]);
                }
            }
        }
    }

    #pragma unroll 2
    for (int h = 0; h < 2; ++h) {
        const int r = row0 + (h ? rB : rA);
        if (r < Gcells) {
            const ull* acc = h ? accB : accA;
            float4* yr = (float4*)(g_Y + (size_t)r * NCP);
            #pragma unroll
            for (int j = 0; j < NCP / 4; ++j) {
                const float2 e = f2unpack(acc[2 * j]);
                const float2 o = f2unpack(acc[2 * j + 1]);
                yr[j] = make_float4(e.x, e.y, o.x, o.y);
            }
        }
    }
}

// ============ K2: out[s] = sigmoid(mean_{p in seg s} Y[idx_p] + b) ============
#define K2_BLOCK 256                      // 8 warps

__global__ void __launch_bounds__(K2_BLOCK)
pool_kernel(const float* __restrict__ bias, const int* __restrict__ point_idx,
            const int* __restrict__ segment_ids, float* __restrict__ out,
            int P, int NC)
{
    __shared__ int    s_b[2];
    __shared__ int    s_i[K2_BLOCK];
    __shared__ float4 s_red[8][32];

    const int tid = threadIdx.x, lane = tid & 31, w = tid >> 5;
    const int seg = blockIdx.x;

    // warps 0,1: 32-ary lower_bound(seg + w) over sorted segment_ids
    if (w < 2) {
        const int target = seg + w;
        int lo = 0, hi = P;
        while (hi - lo > 32) {
            const int step = ((hi - lo) + 31) >> 5;
            int m = lo + lane * step;
            m = min(m, hi - 1);
            const bool lt = (__ldg(&segment_ids[m]) < target);
            const int k = __popc(__ballot_sync(0xffffffffu, lt));
            const int nlo = (k == 0)  ? lo : min(lo + (k - 1) * step + 1, hi);
            const int nhi = (k == 32) ? hi : min(lo + k * step, hi);
            lo = nlo; hi = nhi;
        }
        {
            const int m = lo + lane;
            const bool lt = (m < hi) ? (__ldg(&segment_ids[m]) < target) : false;
            lo += __popc(__ballot_sync(0xffffffffu, lt));
        }
        if (lane == 0) s_b[w] = lo;
    }
    __syncthreads();

    const int start = s_b[0], end = s_b[1], cnt = end - start;

    // lane -> (point-sub, float4 piece): 6 points per warp LDG.128
    const int  psub  = lane / 5;           // 0..6 (6 -> inactive)
    const int  piece = lane - psub * 5;    // 0..4
    const bool gact  = (psub < 6);
    float4 acc = make_float4(0.f, 0.f, 0.f, 0.f);

    for (int base = start; base < end; base += K2_BLOCK) {
        const int n = min(K2_BLOCK, end - base);
        if (tid < n) s_i[tid] = __ldg(&point_idx[base + tid]);
        __syncthreads();
        if (gact) {
            #pragma unroll 2
            for (int i = w * 6 + psub; i < n; i += 48) {
                const int idx = s_i[i];
                const float4 v = __ldg((const float4*)g_Y + (size_t)idx * 5 + piece);
                acc.x += v.x; acc.y += v.y; acc.z += v.z; acc.w += v.w;
            }
        }
        __syncthreads();
    }

    s_red[w][lane] = gact ? acc : make_float4(0.f, 0.f, 0.f, 0.f);
    __syncthreads();

    if (tid < NC) {
        const int pc = tid >> 2, comp = tid & 3;
        float s = 0.f;
        #pragma unroll
        for (int w2 = 0; w2 < 8; ++w2)
            #pragma unroll
            for (int sub = 0; sub < 6; ++sub)
                s += ((const float*)&s_red[w2][sub * 5 + pc])[comp];
        const float x = s / (float)max(cnt, 1) + __ldg(&bias[tid]);
        out[(size_t)seg * NC + tid] = 1.0f / (1.0f + __expf(-x));
    }
}

extern "C" void kernel_launch(void* const* d_in, const int* in_sizes, int n_in,
                              void* d_out, int out_size)
{
    const float* feats       = (const float*)d_in[0];
    const float* Wm          = (const float*)d_in[1];
    const float* bias        = (const float*)d_in[2];
    const int*   point_idx   = (const int*)  d_in[3];
    const int*   segment_ids = (const int*)  d_in[4];
    float*       out         = (float*)      d_out;

    const int NC     = in_sizes[2];              // 19
    const int D      = in_sizes[1] / NC;         // 272
    const int P      = in_sizes[3];              // 524288
    const int NI     = out_size / NC;            // 4096
    const int Gcells = in_sizes[0] / D;          // 65536

    const int k1_smem = (K1_ROWS * K1_FPAD + D * NCP) * (int)sizeof(float);
    static int attr_done = 0;
    if (!attr_done) {
        cudaFuncSetAttribute(project_kernel,
                             cudaFuncAttributeMaxDynamicSharedMemorySize, k1_smem);
        attr_done = 1;
    }

    project_kernel<<<(Gcells + K1_ROWS - 1) / K1_ROWS, K1_BLOCK, k1_smem>>>(
        feats, Wm, D, NC, Gcells);
    pool_kernel<<<NI, K2_BLOCK>>>(bias, point_idx, segment_ids, out, P, NC);
}